// round 5
// baseline (speedup 1.0000x reference)
#include <cuda_runtime.h>
#include <cstdint>

#define Bq 32
#define Nn 64
#define Hh 128
#define Cc 16
#define SIGMA 0.5f
#define PAD 68

typedef unsigned long long ull;

// ---------------- f32x2 packed helpers (sm_103a) ----------------
__device__ __forceinline__ ull ffma2(ull a, ull b, ull c) {
    ull d;
    asm("fma.rn.f32x2 %0, %1, %2, %3;" : "=l"(d) : "l"(a), "l"(b), "l"(c));
    return d;
}
__device__ __forceinline__ ull pack2(float x, float y) {
    ull d;
    asm("mov.b64 %0, {%1, %2};" : "=l"(d) : "f"(x), "f"(y));
    return d;
}
__device__ __forceinline__ float lo2(ull v) { return __uint_as_float((unsigned)v); }
__device__ __forceinline__ float hi2(ull v) { return __uint_as_float((unsigned)(v >> 32)); }

// ---------------- device scratch ----------------
__device__ float g_Anorm[Bq * Nn * Nn];
__device__ float g_h[Bq * Nn * Hh];
__device__ float g_h2[Bq * Nn * Hh];
__device__ unsigned long long g_adjbits[Bq * Nn];
__device__ unsigned long long g_maskbits[Bq];
__device__ int g_maxcl[Bq];

// ====== kernel 1: zero + prep + h1 = x @ W1  (32 blocks, 256 thr) ======
__global__ __launch_bounds__(256) void prep_gemm1(
    const float* __restrict__ x, const float* __restrict__ adj,
    const void* maskp, const float* __restrict__ W1,
    float* __restrict__ outZero, int nzero) {
    int b = blockIdx.x, tid = threadIdx.x;
    __shared__ float deg[Nn];
    __shared__ float xs[Hh * PAD];  // x transposed [h][node]

    for (int idx = b * 256 + tid; idx < nzero; idx += Bq * 256) outZero[idx] = 0.f;
    if (b == 0 && tid < Bq) g_maxcl[tid] = 0;

    if (tid == 0) {
        unsigned first = ((const unsigned*)maskp)[0];
        int mode = (first == 1u) ? 1 : ((first == 0x3F800000u) ? 2 : 0);
        unsigned long long bits = 0;
        for (int j = 0; j < Nn; j++) {
            bool m;
            if (mode == 0)      m = ((const unsigned char*)maskp)[b * Nn + j] != 0;
            else if (mode == 1) m = ((const int*)maskp)[b * Nn + j] != 0;
            else                m = ((const float*)maskp)[b * Nn + j] != 0.f;
            if (m) bits |= 1ull << j;
        }
        g_maskbits[b] = bits;
    }
    if (tid < Nn) {
        float s = 0.f;
        unsigned long long abits = 0;
        const float* arow = adj + (size_t)b * Nn * Nn + (size_t)tid * Nn;
        for (int j = 0; j < Nn; j++) {
            float v = arow[j];
            if (v > 0.f) abits |= 1ull << j;
            s += (j == tid) ? 1.f : v;
        }
        g_adjbits[b * Nn + tid] = abits;
        deg[tid] = rsqrtf(fmaxf(s, 1.f));
    }
    for (int idx = tid; idx < Nn * Hh; idx += 256) {
        int i = idx >> 7, h = idx & 127;
        xs[h * PAD + i] = x[(size_t)b * Nn * Hh + idx];
    }
    __syncthreads();
    for (int idx = tid; idx < Nn * Nn; idx += 256) {
        int i = idx >> 6, j = idx & 63;
        float a = (i == j) ? 1.f : adj[(size_t)b * Nn * Nn + idx];
        g_Anorm[(size_t)b * Nn * Nn + idx] = deg[i] * a * deg[j];
    }
    int ho = tid & 127, rg = tid >> 7, r0 = rg * 32;
    ull acc2[16];
#pragma unroll
    for (int p = 0; p < 16; p++) acc2[p] = 0ull;
#pragma unroll 4
    for (int k = 0; k < Hh; k++) {
        float w = W1[k * Hh + ho];
        ull ww = pack2(w, w);
        const ulonglong2* xr = (const ulonglong2*)(xs + k * PAD + r0);
#pragma unroll
        for (int q = 0; q < 8; q++) {
            ulonglong2 p0 = xr[q];
            acc2[q * 2 + 0] = ffma2(p0.x, ww, acc2[q * 2 + 0]);
            acc2[q * 2 + 1] = ffma2(p0.y, ww, acc2[q * 2 + 1]);
        }
    }
#pragma unroll
    for (int p = 0; p < 16; p++) {
        g_h[((size_t)b * Nn + r0 + 2 * p + 0) * Hh + ho] = lo2(acc2[p]);
        g_h[((size_t)b * Nn + r0 + 2 * p + 1) * Hh + ho] = hi2(acc2[p]);
    }
}

// ====== kernel 2: xe = relu(A@h1+b1)*mask fused with h2 = xe @ W2 ======
__global__ __launch_bounds__(256) void agg1_gemm2(const float* __restrict__ b1,
                                                  const float* __restrict__ W2) {
    int b = blockIdx.x >> 1;
    int r0 = (blockIdx.x & 1) * 32;
    __shared__ float hs[Nn * Hh];
    __shared__ float at[Nn * 36];
    __shared__ float xet[Hh * 36];
    int tid = threadIdx.x;
    for (int idx = tid; idx < Nn * Hh; idx += 256)
        hs[idx] = g_h[(size_t)b * Nn * Hh + idx];
    for (int idx = tid; idx < 32 * Nn; idx += 256) {
        int il = idx >> 6, j = idx & 63;
        at[j * 36 + il] = g_Anorm[((size_t)b * Nn + r0 + il) * Nn + j];
    }
    __syncthreads();
    int ho = tid & 127, half = tid >> 7;
    int i0 = half * 16;
    float bv = b1[ho];
    float acc[16];
#pragma unroll
    for (int q = 0; q < 16; q++) acc[q] = bv;
#pragma unroll 2
    for (int j = 0; j < Nn; j++) {
        float hv = hs[j * Hh + ho];
        const float4* ar = (const float4*)(at + j * 36 + i0);
#pragma unroll
        for (int q = 0; q < 4; q++) {
            float4 v = ar[q];
            acc[q * 4 + 0] += v.x * hv;
            acc[q * 4 + 1] += v.y * hv;
            acc[q * 4 + 2] += v.z * hv;
            acc[q * 4 + 3] += v.w * hv;
        }
    }
    unsigned long long mb = g_maskbits[b];
#pragma unroll
    for (int q = 0; q < 16; q++) {
        int i = r0 + i0 + q;
        float v = ((mb >> i) & 1ull) ? fmaxf(acc[q], 0.f) : 0.f;
        xet[ho * 36 + i0 + q] = v;
    }
    __syncthreads();
    ull acc2[8];
#pragma unroll
    for (int p = 0; p < 8; p++) acc2[p] = 0ull;
#pragma unroll 4
    for (int k = 0; k < Hh; k++) {
        float w = W2[k * Hh + ho];
        ull ww = pack2(w, w);
        const ulonglong2* xr = (const ulonglong2*)(xet + k * 36 + half * 16);
#pragma unroll
        for (int q = 0; q < 4; q++) {
            ulonglong2 p0 = xr[q];
            acc2[q * 2 + 0] = ffma2(p0.x, ww, acc2[q * 2 + 0]);
            acc2[q * 2 + 1] = ffma2(p0.y, ww, acc2[q * 2 + 1]);
        }
    }
#pragma unroll
    for (int p = 0; p < 8; p++) {
        g_h2[((size_t)b * Nn + r0 + half * 16 + 2 * p + 0) * Hh + ho] = lo2(acc2[p]);
        g_h2[((size_t)b * Nn + r0 + half * 16 + 2 * p + 1) * Hh + ho] = hi2(acc2[p]);
    }
}

// ====== kernel 3: x_emb = relu(A@h2 + b2)*mask ======
__global__ __launch_bounds__(256) void agg2(const float* __restrict__ bias,
                                            float* __restrict__ out_p) {
    int b = blockIdx.x >> 1;
    int r0 = (blockIdx.x & 1) * 32;
    __shared__ float hs[Nn * Hh];
    __shared__ float at[Nn * 36];
    int tid = threadIdx.x;
    for (int idx = tid; idx < Nn * Hh; idx += 256)
        hs[idx] = g_h2[(size_t)b * Nn * Hh + idx];
    for (int idx = tid; idx < 32 * Nn; idx += 256) {
        int il = idx >> 6, j = idx & 63;
        at[j * 36 + il] = g_Anorm[((size_t)b * Nn + r0 + il) * Nn + j];
    }
    __syncthreads();
    int ho = tid & 127, half = tid >> 7;
    int i0 = half * 16;
    float bv = bias[ho];
    float acc[16];
#pragma unroll
    for (int q = 0; q < 16; q++) acc[q] = bv;
#pragma unroll 2
    for (int j = 0; j < Nn; j++) {
        float hv = hs[j * Hh + ho];
        const float4* ar = (const float4*)(at + j * 36 + i0);
#pragma unroll
        for (int q = 0; q < 4; q++) {
            float4 v = ar[q];
            acc[q * 4 + 0] += v.x * hv;
            acc[q * 4 + 1] += v.y * hv;
            acc[q * 4 + 2] += v.z * hv;
            acc[q * 4 + 3] += v.w * hv;
        }
    }
    unsigned long long mb = g_maskbits[b];
#pragma unroll
    for (int q = 0; q < 16; q++) {
        int i = r0 + i0 + q;
        float v = ((mb >> i) & 1ull) ? fmaxf(acc[q], 0.f) : 0.f;
        out_p[((size_t)b * Nn + i) * Hh + ho] = v;
    }
}

// ====== kernel 4: main perturbed clustering ======
struct SmemK5 {
    float xa[Hh * PAD];
    float tt[Hh * PAD];
    float xnew[Nn * Hh];
    float lg[Nn * Cc];
    unsigned long long adjraw[Nn];
    unsigned long long reach[Nn];
    unsigned long long nodemask[Nn];
    unsigned long long rowOr[Nn];
    unsigned long long present;
    int concepts[Nn];
    int assign[Nn];
    int ncl;
};

__global__ __launch_bounds__(256, 2) void main_kernel(
    const float* __restrict__ xemb, const float* __restrict__ noise,
    const float* __restrict__ cW1, const float* __restrict__ cb1,
    const float* __restrict__ cW2, const float* __restrict__ cb2,
    float* __restrict__ outXnew, float* __restrict__ outAdj,
    float* __restrict__ outAssign, int S, int NC, float invS) {
    extern __shared__ char smemraw[];
    SmemK5* sm = (SmemK5*)smemraw;
    int tid = threadIdx.x;
    int b = blockIdx.x % Bq;
    int chunk = blockIdx.x / Bq;

    for (int idx = tid; idx < Nn * Hh; idx += 256) sm->xnew[idx] = 0.f;
    if (tid < Nn) sm->adjraw[tid] = g_adjbits[b * Nn + tid];
    unsigned long long mb = g_maskbits[b];
    __syncthreads();

    // MLP tile mapping: 8 nodes x 4 ho per thread
    int tn = tid & 7, th = tid >> 3;
    int n0 = tn * 8, h0 = th * 4;

    for (int s = chunk; s < S; s += NC) {
        int bs = s * Bq + b;

        // ---- load x_all = x_emb + sigma*noise, transposed ----
        const float* xb = xemb + (size_t)b * Nn * Hh;
        const float* nz = noise + (size_t)bs * Nn * Hh;
#pragma unroll 8
        for (int idx = tid; idx < Nn * Hh; idx += 256) {
            int i = idx >> 7, h = idx & 127;
            sm->xa[h * PAD + i] = xb[idx] + SIGMA * nz[idx];
        }
        __syncthreads();

        // ---- t = relu(x_all @ cW1 + cb1): 8n x 4h tile per thread ----
        // per k: 32B LDS (node pairs, warp-broadcast) + 16B LDG (w float4)
        {
            ull acc[4][4];  // [h][node-pair]
            float4 bv = *(const float4*)(cb1 + h0);
            const float* bp = (const float*)&bv;
#pragma unroll
            for (int h = 0; h < 4; h++) {
                ull bi = pack2(bp[h], bp[h]);
#pragma unroll
                for (int np = 0; np < 4; np++) acc[h][np] = bi;
            }
#pragma unroll 2
            for (int k = 0; k < Hh; k++) {
                const ulonglong2* xr = (const ulonglong2*)(sm->xa + k * PAD + n0);
                ulonglong2 x01 = xr[0];
                ulonglong2 x23 = xr[1];
                float4 wv = *(const float4*)(cW1 + k * Hh + h0);
                const float* wp = (const float*)&wv;
#pragma unroll
                for (int h = 0; h < 4; h++) {
                    ull wb = pack2(wp[h], wp[h]);
                    acc[h][0] = ffma2(x01.x, wb, acc[h][0]);
                    acc[h][1] = ffma2(x01.y, wb, acc[h][1]);
                    acc[h][2] = ffma2(x23.x, wb, acc[h][2]);
                    acc[h][3] = ffma2(x23.y, wb, acc[h][3]);
                }
            }
#pragma unroll
            for (int h = 0; h < 4; h++) {
                float4 v0, v1;
                v0.x = fmaxf(lo2(acc[h][0]), 0.f);
                v0.y = fmaxf(hi2(acc[h][0]), 0.f);
                v0.z = fmaxf(lo2(acc[h][1]), 0.f);
                v0.w = fmaxf(hi2(acc[h][1]), 0.f);
                v1.x = fmaxf(lo2(acc[h][2]), 0.f);
                v1.y = fmaxf(hi2(acc[h][2]), 0.f);
                v1.z = fmaxf(lo2(acc[h][3]), 0.f);
                v1.w = fmaxf(hi2(acc[h][3]), 0.f);
                float4* to = (float4*)(sm->tt + (h0 + h) * PAD + n0);
                to[0] = v0;
                to[1] = v1;
            }
        }
        __syncthreads();

        // ---- logits = t @ cW2 + cb2 (FFMA2, cW2 via L1) ----
        {
            int i = tid & 63, cg = tid >> 6;
            ull a01 = pack2(cb2[cg * 4 + 0], cb2[cg * 4 + 1]);
            ull a23 = pack2(cb2[cg * 4 + 2], cb2[cg * 4 + 3]);
#pragma unroll 4
            for (int k = 0; k < Hh; k++) {
                float tv = sm->tt[k * PAD + i];
                ull tvv = pack2(tv, tv);
                ulonglong2 cv = ((const ulonglong2*)(cW2 + k * Cc + cg * 4))[0];
                a01 = ffma2(tvv, cv.x, a01);
                a23 = ffma2(tvv, cv.y, a23);
            }
            sm->lg[i * Cc + cg * 4 + 0] = lo2(a01);
            sm->lg[i * Cc + cg * 4 + 1] = hi2(a01);
            sm->lg[i * Cc + cg * 4 + 2] = lo2(a23);
            sm->lg[i * Cc + cg * 4 + 3] = hi2(a23);
        }
        __syncthreads();

        // ---- argmax ----
        if (tid < Nn) {
            float best = sm->lg[tid * Cc];
            int bi = 0;
            for (int c = 1; c < Cc; c++) {
                float v = sm->lg[tid * Cc + c];
                if (v > best) { best = v; bi = c; }
            }
            sm->concepts[tid] = bi;
        }
        __syncthreads();

        // ---- edges + reach init ----
        if (tid < Nn) {
            int ci = sm->concepts[tid];
            unsigned long long cm = 0;
            for (int j = 0; j < Nn; j++)
                if (sm->concepts[j] == ci) cm |= 1ull << j;
            bool mi = (mb >> tid) & 1ull;
            unsigned long long e = mi ? (sm->adjraw[tid] & cm & mb) : 0ull;
            sm->reach[tid] = e | (1ull << tid);
        }
        __syncthreads();

        // ---- transitive closure by squaring ----
        for (int it = 0; it < 6; it++) {
            unsigned long long r = 0;
            if (tid < Nn) {
                unsigned long long cur = sm->reach[tid];
                r = cur;
                unsigned long long t2 = cur;
                while (t2) {
                    int j = __ffsll((long long)t2) - 1;
                    r |= sm->reach[j];
                    t2 &= t2 - 1;
                }
            }
            __syncthreads();
            if (tid < Nn) sm->reach[tid] = r;
            __syncthreads();
        }

        // ---- roots -> present -> rank -> assignments ----
        if (tid == 0) { sm->present = 0ull; sm->ncl = 0; }
        if (tid < Nn) sm->nodemask[tid] = 0ull;
        __syncthreads();
        int root = 0;
        bool mi = false;
        if (tid < Nn) {
            mi = (mb >> tid) & 1ull;
            if (mi) {
                root = __ffsll((long long)sm->reach[tid]) - 1;
                atomicOr(&sm->present, 1ull << root);
            }
        }
        __syncthreads();
        if (tid < Nn) {
            int a = 0;
            if (mi) {
                unsigned long long pm =
                    sm->present & (0xFFFFFFFFFFFFFFFFull >> (63 - root));
                a = __popcll(pm);
                atomicOr(&sm->nodemask[a - 1], 1ull << tid);
                atomicMax(&sm->ncl, a);
            }
            sm->assign[tid] = a;
            outAssign[(size_t)bs * Nn + tid] = (float)a;
        }
        __syncthreads();
        if (tid == 0) atomicMax(&g_maxcl[b], sm->ncl);

        // ---- cluster row-OR ----
        if (tid < Nn) {
            unsigned long long nm = sm->nodemask[tid];
            unsigned long long ro = 0, t2 = nm;
            while (t2) {
                int j = __ffsll((long long)t2) - 1;
                ro |= sm->adjraw[j];
                t2 &= t2 - 1;
            }
            sm->rowOr[tid] = ro;
        }
        __syncthreads();

        // ---- cluster-adjacency -> global atomics; x_new sums -> smem ----
        if (tid < Nn) {
            if (sm->nodemask[tid]) {
                unsigned long long ro = sm->rowOr[tid];
                float* arow = outAdj + (size_t)b * Nn * Nn + (size_t)tid * Nn;
                for (int c2 = 0; c2 < Nn; c2++)
                    if (ro & sm->nodemask[c2]) atomicAdd(&arow[c2], invS);
            }
        }
        if (tid < Hh) {
            int h = tid;
            for (int i2 = 0; i2 < Nn; i2++) {
                int ai = sm->assign[i2];
                if (ai > 0) sm->xnew[(ai - 1) * Hh + h] += sm->xa[h * PAD + i2];
            }
        }
        __syncthreads();
    }

    // ---- flush x_new accumulator ----
    for (int idx = tid; idx < Nn * Hh; idx += 256) {
        float v = sm->xnew[idx];
        if (v != 0.f) atomicAdd(&outXnew[(size_t)b * Nn * Hh + idx], v * invS);
    }
}

// ====== kernel 5: mask_new ======
__global__ void finish_kernel(float* outMask) {
    int idx = blockIdx.x * blockDim.x + threadIdx.x;
    if (idx < Bq * Nn) {
        int b = idx / Nn, j = idx % Nn;
        outMask[idx] = (j < g_maxcl[b]) ? 1.f : 0.f;
    }
}

// ---------------- host launcher ----------------
extern "C" void kernel_launch(void* const* d_in, const int* in_sizes, int n_in,
                              void* d_out, int out_size) {
    const float* x   = (const float*)d_in[0];
    const float* adj = (const float*)d_in[1];
    const void*  msk = d_in[2];
    const float* W1  = (const float*)d_in[3];
    const float* b1  = (const float*)d_in[4];
    const float* W2  = (const float*)d_in[5];
    const float* b2  = (const float*)d_in[6];
    const float* cW1 = (const float*)d_in[7];
    const float* cb1 = (const float*)d_in[8];
    const float* cW2 = (const float*)d_in[9];
    const float* cb2 = (const float*)d_in[10];
    const float* noise = (const float*)d_in[11];

    int S = in_sizes[11] / in_sizes[0];
    if (S <= 0) S = 1;

    float* out = (float*)d_out;
    size_t offAdj    = (size_t)Bq * Nn * Hh;
    size_t offAssign = offAdj + (size_t)Bq * Nn * Nn;
    size_t offXemb   = offAssign + (size_t)S * Bq * Nn;
    size_t offMask   = offXemb + (size_t)Bq * Nn * Hh;

    cudaFuncSetAttribute(main_kernel, cudaFuncAttributeMaxDynamicSharedMemorySize,
                         (int)sizeof(SmemK5));

    // #1: zero + prep + h1
    prep_gemm1<<<Bq, 256>>>(x, adj, msk, W1, out, (int)offAssign);
    // #2: xe + h2 (fused)
    agg1_gemm2<<<Bq * 2, 256>>>(b1, W2);
    // #3: x_emb
    agg2<<<Bq * 2, 256>>>(b2, out + offXemb);
    // #4: main (ncu capture slot)
    int NC = (S < 28) ? S : 28;
    main_kernel<<<NC * Bq, 256, sizeof(SmemK5)>>>(
        out + offXemb, noise, cW1, cb1, cW2, cb2,
        out, out + offAdj, out + offAssign, S, NC, 1.0f / (float)S);
    // #5: mask_new
    finish_kernel<<<(Bq * Nn + 255) / 256, 256>>>(out + offMask);
}